// round 3
// baseline (speedup 1.0000x reference)
#include <cuda_runtime.h>
#include <cstdint>
#include <cstddef>

// Problem constants (SparseLoRAMoE): B=4, S=4096 -> N=16384 tokens
#define N_TOK 16384
#define DIM   4096
#define NEXP  8
#define RANK  16
#define OUT_D 4096
#define SCALING 0.5f
#define NW1 136          // 128 LoRA-A rows + 8 router rows

// -------- scratch (static device allocation; no cudaMalloc allowed) --------
__device__ float g_hw[(size_t)N_TOK * 128];   // gated h, fp32, 8.4 MB

// -------- helpers --------
__device__ __forceinline__ uint32_t f2tf(float f) {
    uint32_t u;
    asm("cvt.rna.tf32.f32 %0, %1;" : "=r"(u) : "f"(f));
    return u;
}

__device__ __forceinline__ void mma_tf32(float* c, const uint32_t* a,
                                         uint32_t b0, uint32_t b1) {
    asm volatile(
        "mma.sync.aligned.m16n8k8.row.col.f32.tf32.tf32.f32 "
        "{%0,%1,%2,%3}, {%4,%5,%6,%7}, {%8,%9}, {%0,%1,%2,%3};\n"
        : "+f"(c[0]), "+f"(c[1]), "+f"(c[2]), "+f"(c[3])
        : "r"(a[0]), "r"(a[1]), "r"(a[2]), "r"(a[3]), "r"(b0), "r"(b1));
}

// ============================================================================
// GEMM1: C[N,136] = X[N,4096] @ W1[136,4096]^T  (W1 = [A_flat; router_w])
// Logits columns (128..135) use error-compensated tf32 (hi/lo split, 3 MMAs)
// so top-2 selection matches fp32 reference.
// Fused epilogue: softmax/top2/renorm gates -> hw[N,128] to g_hw.
// ============================================================================
#define BK1     32
#define STR1    36                              // 32 + pad4: conflict-free frags
#define AS_SZ   (2 * 128 * STR1)                // 9216 floats
#define WS_SZ   (2 * NW1 * STR1)                // 9792 floats
#define ASLO_SZ (2 * 128 * STR1)                // 9216 floats (x residuals)
#define WSLO_SZ (2 * NEXP * STR1)               // 576 floats (router residuals)
#define SM1_FLOATS (AS_SZ + WS_SZ + ASLO_SZ + WSLO_SZ + 128 * 8)

__global__ __launch_bounds__(256, 1)
void gemm1_router_kernel(const float* __restrict__ x,
                         const float* __restrict__ rw,
                         const float* __restrict__ rb,
                         const float* __restrict__ A)
{
    extern __shared__ float sm[];
    float* As   = sm;                                  // [2][128][STR1]
    float* Ws   = sm + AS_SZ;                          // [2][136][STR1]
    float* AsLo = sm + AS_SZ + WS_SZ;                  // [2][128][STR1]
    float* WsLo = sm + AS_SZ + WS_SZ + ASLO_SZ;        // [2][8][STR1]
    float* gw   = sm + AS_SZ + WS_SZ + ASLO_SZ + WSLO_SZ; // [128][8]

    const int tid  = threadIdx.x;
    const int lane = tid & 31;
    const int warp = tid >> 5;
    const int wm   = warp & 3;          // 0..3: 32-row slab
    const int wn   = warp >> 2;         // 0..1: cols 0..63 / 64..135
    const int g    = lane >> 2;         // groupID
    const int tig  = lane & 3;          // thread-in-group
    const int m0   = blockIdx.x * 128;
    const int ncol0 = wn * 64;

    float acc[2][9][4];
#pragma unroll
    for (int mt = 0; mt < 2; mt++)
#pragma unroll
        for (int nt = 0; nt < 9; nt++)
#pragma unroll
            for (int i = 0; i < 4; i++) acc[mt][nt][i] = 0.f;

    float4 ar[4];   // A-tile staging
    float4 br[5];   // W-tile staging

    // ---- prologue loads (k0 = 0) ----
#pragma unroll
    for (int i = 0; i < 4; i++) {
        int idx = tid + i * 256, row = idx >> 3, c4 = idx & 7;
        ar[i] = *(const float4*)(x + (size_t)(m0 + row) * DIM + 4 * c4);
    }
#pragma unroll
    for (int i = 0; i < 5; i++) {
        int idx = tid + i * 256;
        if (idx < NW1 * 8) {
            int row = idx >> 3, c4 = idx & 7;
            const float* src = (row < 128) ? (A + (size_t)row * DIM)
                                           : (rw + (size_t)(row - 128) * DIM);
            br[i] = *(const float4*)(src + 4 * c4);
        }
    }

    const int T = DIM / BK1;   // 128 iterations
    for (int t = 0; t < T; ++t) {
        const int buf = t & 1;
        // ---- STS: split into tf32 hi (rna) + residual lo ----
        {
            float* a  = As   + buf * 128 * STR1;
            float* al = AsLo + buf * 128 * STR1;
#pragma unroll
            for (int i = 0; i < 4; i++) {
                int idx = tid + i * 256, row = idx >> 3, c4 = idx & 7;
                uint32_t* p  = (uint32_t*)(a  + row * STR1 + 4 * c4);
                uint32_t* pl = (uint32_t*)(al + row * STR1 + 4 * c4);
                float v[4] = {ar[i].x, ar[i].y, ar[i].z, ar[i].w};
#pragma unroll
                for (int j = 0; j < 4; j++) {
                    uint32_t hi = f2tf(v[j]);
                    p[j]  = hi;
                    pl[j] = f2tf(v[j] - __uint_as_float(hi));
                }
            }
            float* w  = Ws   + buf * NW1 * STR1;
            float* wl = WsLo + buf * NEXP * STR1;
#pragma unroll
            for (int i = 0; i < 5; i++) {
                int idx = tid + i * 256;
                if (idx < NW1 * 8) {
                    int row = idx >> 3, c4 = idx & 7;
                    uint32_t* p = (uint32_t*)(w + row * STR1 + 4 * c4);
                    float v[4] = {br[i].x, br[i].y, br[i].z, br[i].w};
                    if (row < 128) {
#pragma unroll
                        for (int j = 0; j < 4; j++) p[j] = f2tf(v[j]);
                    } else {
                        uint32_t* pl = (uint32_t*)(wl + (row - 128) * STR1 + 4 * c4);
#pragma unroll
                        for (int j = 0; j < 4; j++) {
                            uint32_t hi = f2tf(v[j]);
                            p[j]  = hi;
                            pl[j] = f2tf(v[j] - __uint_as_float(hi));
                        }
                    }
                }
            }
        }
        __syncthreads();

        // ---- prefetch next tile ----
        if (t + 1 < T) {
            const int k0 = (t + 1) * BK1;
#pragma unroll
            for (int i = 0; i < 4; i++) {
                int idx = tid + i * 256, row = idx >> 3, c4 = idx & 7;
                ar[i] = *(const float4*)(x + (size_t)(m0 + row) * DIM + k0 + 4 * c4);
            }
#pragma unroll
            for (int i = 0; i < 5; i++) {
                int idx = tid + i * 256;
                if (idx < NW1 * 8) {
                    int row = idx >> 3, c4 = idx & 7;
                    const float* src = (row < 128) ? (A + (size_t)row * DIM)
                                                   : (rw + (size_t)(row - 128) * DIM);
                    br[i] = *(const float4*)(src + k0 + 4 * c4);
                }
            }
        }

        // ---- compute 4 k-steps from SMEM ----
        const uint32_t* a  = (const uint32_t*)(As   + buf * 128 * STR1);
        const uint32_t* al = (const uint32_t*)(AsLo + buf * 128 * STR1);
        const uint32_t* w  = (const uint32_t*)(Ws   + buf * NW1 * STR1);
        const uint32_t* wl = (const uint32_t*)(WsLo + buf * NEXP * STR1);
#pragma unroll
        for (int ks = 0; ks < 4; ++ks) {
            const int k = ks * 8;
            uint32_t af[2][4];
#pragma unroll
            for (int mt = 0; mt < 2; ++mt) {
                const int rbase = wm * 32 + mt * 16;
                af[mt][0] = a[(rbase + g)     * STR1 + k + tig];
                af[mt][1] = a[(rbase + g + 8) * STR1 + k + tig];
                af[mt][2] = a[(rbase + g)     * STR1 + k + tig + 4];
                af[mt][3] = a[(rbase + g + 8) * STR1 + k + tig + 4];
            }
#pragma unroll
            for (int nt = 0; nt < 8; ++nt) {
                const int n = ncol0 + nt * 8 + g;
                uint32_t b0 = w[n * STR1 + k + tig];
                uint32_t b1 = w[n * STR1 + k + tig + 4];
                mma_tf32(acc[0][nt], af[0], b0, b1);
                mma_tf32(acc[1][nt], af[1], b0, b1);
            }
            if (wn == 1) {
                // logits tile: compensated tf32 (hi*hi + hi*lo + lo*hi)
                uint32_t aflo[2][4];
#pragma unroll
                for (int mt = 0; mt < 2; ++mt) {
                    const int rbase = wm * 32 + mt * 16;
                    aflo[mt][0] = al[(rbase + g)     * STR1 + k + tig];
                    aflo[mt][1] = al[(rbase + g + 8) * STR1 + k + tig];
                    aflo[mt][2] = al[(rbase + g)     * STR1 + k + tig + 4];
                    aflo[mt][3] = al[(rbase + g + 8) * STR1 + k + tig + 4];
                }
                const int n = 128 + g;                       // router row g
                uint32_t b0   = w[n * STR1 + k + tig];
                uint32_t b1   = w[n * STR1 + k + tig + 4];
                uint32_t b0lo = wl[g * STR1 + k + tig];
                uint32_t b1lo = wl[g * STR1 + k + tig + 4];
                mma_tf32(acc[0][8], af[0], b0, b1);
                mma_tf32(acc[1][8], af[1], b0, b1);
                mma_tf32(acc[0][8], af[0], b0lo, b1lo);
                mma_tf32(acc[1][8], af[1], b0lo, b1lo);
                mma_tf32(acc[0][8], aflo[0], b0, b1);
                mma_tf32(acc[1][8], aflo[1], b0, b1);
            }
        }
        __syncthreads();
    }

    // ---- epilogue: router softmax -> top2 -> renorm gates (wn==1 owns logits) ----
    if (wn == 1) {
        const float rb0 = rb[2 * tig];
        const float rb1 = rb[2 * tig + 1];
#pragma unroll
        for (int mt = 0; mt < 2; ++mt) {
#pragma unroll
            for (int half = 0; half < 2; ++half) {
                float l0 = acc[mt][8][half * 2 + 0] + rb0;  // expert 2*tig
                float l1 = acc[mt][8][half * 2 + 1] + rb1;  // expert 2*tig+1
                float m1, m2; int i1, i2;
                if (l0 >= l1) { m1 = l0; i1 = 2 * tig;     m2 = l1; i2 = 2 * tig + 1; }
                else          { m1 = l1; i1 = 2 * tig + 1; m2 = l0; i2 = 2 * tig; }
#pragma unroll
                for (int d = 1; d <= 2; d <<= 1) {
                    float om1 = __shfl_xor_sync(0xffffffffu, m1, d);
                    int   oi1 = __shfl_xor_sync(0xffffffffu, i1, d);
                    float om2 = __shfl_xor_sync(0xffffffffu, m2, d);
                    int   oi2 = __shfl_xor_sync(0xffffffffu, i2, d);
                    if (om1 > m1) {
                        if (m1 >= om2) { m2 = m1; i2 = i1; }
                        else           { m2 = om2; i2 = oi2; }
                        m1 = om1; i1 = oi1;
                    } else if (om1 > m2) { m2 = om1; i2 = oi1; }
                }
                // gates = softmax(top2)/sum = sigmoid(l1 - l2)
                float g1 = 1.f / (1.f + __expf(m2 - m1));
                float g2 = 1.f - g1;
                int row = wm * 32 + mt * 16 + half * 8 + g;
                gw[row * 8 + 2 * tig]     = (2 * tig     == i1) ? g1 : ((2 * tig     == i2) ? g2 : 0.f);
                gw[row * 8 + 2 * tig + 1] = (2 * tig + 1 == i1) ? g1 : ((2 * tig + 1 == i2) ? g2 : 0.f);
            }
        }
    }
    __syncthreads();

    // ---- scale h by gates and store hw (nt<8 only; logits never stored) ----
#pragma unroll
    for (int mt = 0; mt < 2; ++mt) {
#pragma unroll
        for (int nt = 0; nt < 8; ++nt) {
            const int col = ncol0 + nt * 8 + 2 * tig;   // 0..127 always
            const int e  = col >> 4;
            const int ra = wm * 32 + mt * 16 + g;
            const int rb_ = ra + 8;
            const float wa = gw[ra * 8 + e];
            const float wb = gw[rb_ * 8 + e];
            float2 va = make_float2(acc[mt][nt][0] * wa, acc[mt][nt][1] * wa);
            float2 vb = make_float2(acc[mt][nt][2] * wb, acc[mt][nt][3] * wb);
            *(float2*)(g_hw + (size_t)(m0 + ra)  * 128 + col) = va;
            *(float2*)(g_hw + (size_t)(m0 + rb_) * 128 + col) = vb;
        }
    }
}

// ============================================================================
// GEMM2: out[N,4096] = hw[N,128] @ Bt[4096,128]^T,
// Bt[o, e*16+r] = Bm[e,o,r] * SCALING, gathered from Bm at load time.
// ============================================================================
#define STR2 132                               // 128 + pad4
#define SM2_FLOATS (2 * 128 * STR2)

__global__ __launch_bounds__(256, 1)
void gemm2_kernel(const float* __restrict__ Bm, float* __restrict__ out)
{
    extern __shared__ float sm[];
    float* Hs = sm;                  // [128][STR2]  rows = tokens
    float* Bs = sm + 128 * STR2;     // [128][STR2]  rows = out cols

    const int tid  = threadIdx.x;
    const int lane = tid & 31;
    const int warp = tid >> 5;
    const int wm   = warp & 3;
    const int wn   = warp >> 2;
    const int g    = lane >> 2;
    const int tig  = lane & 3;
    const int m0   = blockIdx.y * 128;
    const int n0   = blockIdx.x * 128;

    // ---- load hw tile (batched for MLP), cvt to tf32 ----
    {
        float4 tmp[16];
#pragma unroll
        for (int i = 0; i < 16; i++) {
            int idx = tid + i * 256, row = idx >> 5, c4 = idx & 31;
            tmp[i] = *(const float4*)(g_hw + (size_t)(m0 + row) * 128 + 4 * c4);
        }
#pragma unroll
        for (int i = 0; i < 16; i++) {
            int idx = tid + i * 256, row = idx >> 5, c4 = idx & 31;
            uint32_t* p = (uint32_t*)(Hs + row * STR2 + 4 * c4);
            p[0] = f2tf(tmp[i].x); p[1] = f2tf(tmp[i].y);
            p[2] = f2tf(tmp[i].z); p[3] = f2tf(tmp[i].w);
        }
        // ---- gather Bt tile from Bm [E,O,R], fold SCALING ----
#pragma unroll
        for (int i = 0; i < 16; i++) {
            int idx = tid + i * 256, row = idx >> 5, c4 = idx & 31;
            int k = 4 * c4, e = k >> 4, r = k & 15;
            tmp[i] = *(const float4*)(Bm + (size_t)e * (OUT_D * RANK)
                                         + (size_t)(n0 + row) * RANK + r);
        }
#pragma unroll
        for (int i = 0; i < 16; i++) {
            int idx = tid + i * 256, row = idx >> 5, c4 = idx & 31;
            uint32_t* p = (uint32_t*)(Bs + row * STR2 + 4 * c4);
            p[0] = f2tf(tmp[i].x * SCALING); p[1] = f2tf(tmp[i].y * SCALING);
            p[2] = f2tf(tmp[i].z * SCALING); p[3] = f2tf(tmp[i].w * SCALING);
        }
    }
    __syncthreads();

    float acc[2][8][4];
#pragma unroll
    for (int mt = 0; mt < 2; mt++)
#pragma unroll
        for (int nt = 0; nt < 8; nt++)
#pragma unroll
            for (int i = 0; i < 4; i++) acc[mt][nt][i] = 0.f;

    const uint32_t* hs = (const uint32_t*)Hs;
    const uint32_t* bs = (const uint32_t*)Bs;
#pragma unroll
    for (int ks = 0; ks < 16; ++ks) {
        const int k = ks * 8;
        uint32_t af[2][4];
#pragma unroll
        for (int mt = 0; mt < 2; ++mt) {
            const int rbase = wm * 32 + mt * 16;
            af[mt][0] = hs[(rbase + g)     * STR2 + k + tig];
            af[mt][1] = hs[(rbase + g + 8) * STR2 + k + tig];
            af[mt][2] = hs[(rbase + g)     * STR2 + k + tig + 4];
            af[mt][3] = hs[(rbase + g + 8) * STR2 + k + tig + 4];
        }
#pragma unroll
        for (int nt = 0; nt < 8; ++nt) {
            const int n = wn * 64 + nt * 8 + g;
            uint32_t b0 = bs[n * STR2 + k + tig];
            uint32_t b1 = bs[n * STR2 + k + tig + 4];
            mma_tf32(acc[0][nt], af[0], b0, b1);
            mma_tf32(acc[1][nt], af[1], b0, b1);
        }
    }

    // ---- store ----
#pragma unroll
    for (int mt = 0; mt < 2; ++mt) {
#pragma unroll
        for (int nt = 0; nt < 8; ++nt) {
            const int col = n0 + wn * 64 + nt * 8 + 2 * tig;
            const int ra  = m0 + wm * 32 + mt * 16 + g;
            *(float2*)(out + (size_t)ra * OUT_D + col) =
                make_float2(acc[mt][nt][0], acc[mt][nt][1]);
            *(float2*)(out + (size_t)(ra + 8) * OUT_D + col) =
                make_float2(acc[mt][nt][2], acc[mt][nt][3]);
        }
    }
}

// ============================================================================
extern "C" void kernel_launch(void* const* d_in, const int* in_sizes, int n_in,
                              void* d_out, int out_size)
{
    const float* x  = (const float*)d_in[0];   // [N, 4096]
    const float* rw = (const float*)d_in[1];   // [8, 4096]
    const float* rb = (const float*)d_in[2];   // [8]
    const float* A  = (const float*)d_in[3];   // [8,16,4096] == [128,4096]
    const float* Bm = (const float*)d_in[4];   // [8,4096,16]
    float* out = (float*)d_out;                // [N, 4096] fp32

    const int sm1 = SM1_FLOATS * (int)sizeof(float);   // ~159 KB
    const int sm2 = SM2_FLOATS * (int)sizeof(float);   // 135168 B
    cudaFuncSetAttribute(gemm1_router_kernel,
                         cudaFuncAttributeMaxDynamicSharedMemorySize, sm1);
    cudaFuncSetAttribute(gemm2_kernel,
                         cudaFuncAttributeMaxDynamicSharedMemorySize, sm2);

    gemm1_router_kernel<<<N_TOK / 128, 256, sm1>>>(x, rw, rb, A);
    gemm2_kernel<<<dim3(OUT_D / 128, N_TOK / 128), 256, sm2>>>(Bm, out);
}

// round 4
// speedup vs baseline: 1.2267x; 1.2267x over previous
#include <cuda_runtime.h>
#include <cstdint>
#include <cstddef>

// Problem constants: B=4, S=4096 -> N=16384 tokens
#define N_TOK 16384
#define DIM   4096
#define OUT_D 4096
#define SCALING 0.5f

// -------- static scratch (no cudaMalloc allowed) --------
__device__ uint32_t g_w1[144 * 4096];          // rows 0-127: A tf32; 128-135: router hi; 136-143: router lo
__device__ uint32_t g_bt[4096 * 128];          // Bt[o][e*16+r] = tf32(Bm[e][o][r]*SCALING)
__device__ uint32_t g_hw[(size_t)N_TOK * 128]; // gated h, tf32 bits

// -------- helpers --------
__device__ __forceinline__ uint32_t f2tf(float f) {
    uint32_t u;
    asm("cvt.rna.tf32.f32 %0, %1;" : "=r"(u) : "f"(f));
    return u;
}

__device__ __forceinline__ void mma_tf32(float* c, const uint32_t* a,
                                         uint32_t b0, uint32_t b1) {
    asm volatile(
        "mma.sync.aligned.m16n8k8.row.col.f32.tf32.tf32.f32 "
        "{%0,%1,%2,%3}, {%4,%5,%6,%7}, {%8,%9}, {%0,%1,%2,%3};\n"
        : "+f"(c[0]), "+f"(c[1]), "+f"(c[2]), "+f"(c[3])
        : "r"(a[0]), "r"(a[1]), "r"(a[2]), "r"(a[3]), "r"(b0), "r"(b1));
}

__device__ __forceinline__ void cp16(void* dst, const void* src) {
    uint32_t d = (uint32_t)__cvta_generic_to_shared(dst);
    asm volatile("cp.async.cg.shared.global [%0], [%1], 16;" :: "r"(d), "l"(src));
}
#define CP_COMMIT() asm volatile("cp.async.commit_group;")
#define CP_WAIT(n)  asm volatile("cp.async.wait_group %0;" :: "n"(n))

// ============================================================================
// Prep: build tf32 operand tensors once.
// ============================================================================
__global__ void prep_kernel(const float* __restrict__ rw,
                            const float* __restrict__ A,
                            const float* __restrict__ Bm)
{
    const int nthr = gridDim.x * blockDim.x;
    const int tid0 = blockIdx.x * blockDim.x + threadIdx.x;
    for (int i = tid0; i < 144 * 4096; i += nthr) {
        int row = i >> 12, col = i & 4095;
        if (row < 128)       g_w1[i] = f2tf(A[i]);
        else if (row < 136)  g_w1[i] = f2tf(rw[(row - 128) * 4096 + col]);
        else {
            float v = rw[(row - 136) * 4096 + col];
            uint32_t hi = f2tf(v);
            g_w1[i] = f2tf(v - __uint_as_float(hi));
        }
    }
    for (int i = tid0; i < 4096 * 128; i += nthr) {
        int o = i >> 7, c = i & 127, e = c >> 4, r = c & 15;
        g_bt[i] = f2tf(Bm[((size_t)e * 4096 + o) * 16 + r] * SCALING);
    }
}

// ============================================================================
// GEMM1: C[N,136] = X @ [A;router]^T, compensated-tf32 logits, fused gating.
// 4-stage cp.async ring, XOR-swizzled SMEM, cvt-at-fragment-load.
// SMEM: As[4][128][32] raw x + Ws[4][144][32] tf32 + gw[128][8]
// ============================================================================
#define SM1_WORDS (4 * 128 * 32 + 4 * 144 * 32 + 1024)

__global__ __launch_bounds__(256, 1)
void gemm1_kernel(const float* __restrict__ x, const float* __restrict__ rb)
{
    extern __shared__ uint32_t smu[];
    uint32_t* As = smu;                 // raw x bits
    uint32_t* Ws = smu + 4 * 128 * 32;  // tf32 W rows (144)
    float*    gw = (float*)(smu + 4 * 128 * 32 + 4 * 144 * 32);

    const int tid  = threadIdx.x;
    const int lane = tid & 31;
    const int warp = tid >> 5;
    const int wm   = warp & 3;
    const int wn   = warp >> 2;
    const int g    = lane >> 2;
    const int tig  = lane & 3;
    const int m0   = blockIdx.x * 128;
    const int ncol0 = wn * 64;

    float acc[2][9][4];
#pragma unroll
    for (int mt = 0; mt < 2; mt++)
#pragma unroll
        for (int nt = 0; nt < 9; nt++)
#pragma unroll
            for (int i = 0; i < 4; i++) acc[mt][nt][i] = 0.f;

    auto issue = [&](int stage, int t) {
        const int k0 = t * 32;
        uint32_t* ab = As + stage * 128 * 32;
        uint32_t* wb = Ws + stage * 144 * 32;
#pragma unroll
        for (int i = 0; i < 4; i++) {
            int idx = tid + i * 256, row = idx >> 3, c4 = idx & 7;
            int col = (4 * c4) ^ ((row & 7) * 4);
            cp16(ab + row * 32 + col, x + (size_t)(m0 + row) * DIM + k0 + 4 * c4);
        }
#pragma unroll
        for (int i = 0; i < 5; i++) {
            int idx = tid + i * 256;
            if (idx < 144 * 8) {
                int row = idx >> 3, c4 = idx & 7;
                int col = (4 * c4) ^ ((row & 7) * 4);
                cp16(wb + row * 32 + col, g_w1 + row * 4096 + k0 + 4 * c4);
            }
        }
    };

    issue(0, 0); CP_COMMIT();
    issue(1, 1); CP_COMMIT();
    issue(2, 2); CP_COMMIT();

    const int T = DIM / 32;   // 128
    for (int t = 0; t < T; ++t) {
        CP_WAIT(2);
        __syncthreads();
        if (t + 3 < T) issue((t + 3) & 3, t + 3);
        CP_COMMIT();

        const uint32_t* a = As + (t & 3) * 128 * 32;
        const uint32_t* w = Ws + (t & 3) * 144 * 32;
#pragma unroll
        for (int ks = 0; ks < 4; ++ks) {
            const int k = ks * 8;
            const int c0 = (k + tig)     ^ (g * 4);
            const int c1 = (k + tig + 4) ^ (g * 4);
            uint32_t af[2][4];
            float raw[2][4];
#pragma unroll
            for (int mt = 0; mt < 2; ++mt) {
                const int r0 = wm * 32 + mt * 16 + g;
                raw[mt][0] = __uint_as_float(a[r0 * 32 + c0]);
                raw[mt][1] = __uint_as_float(a[(r0 + 8) * 32 + c0]);
                raw[mt][2] = __uint_as_float(a[r0 * 32 + c1]);
                raw[mt][3] = __uint_as_float(a[(r0 + 8) * 32 + c1]);
#pragma unroll
                for (int j = 0; j < 4; j++) af[mt][j] = f2tf(raw[mt][j]);
            }
#pragma unroll
            for (int nt = 0; nt < 8; ++nt) {
                const int n = ncol0 + nt * 8 + g;     // n&7 == g
                uint32_t b0 = w[n * 32 + c0];
                uint32_t b1 = w[n * 32 + c1];
                mma_tf32(acc[0][nt], af[0], b0, b1);
                mma_tf32(acc[1][nt], af[1], b0, b1);
            }
            if (wn == 1) {
                uint32_t alo[2][4];
#pragma unroll
                for (int mt = 0; mt < 2; ++mt)
#pragma unroll
                    for (int j = 0; j < 4; j++)
                        alo[mt][j] = f2tf(raw[mt][j] - __uint_as_float(af[mt][j]));
                uint32_t b0 = w[(128 + g) * 32 + c0];
                uint32_t b1 = w[(128 + g) * 32 + c1];
                uint32_t l0 = w[(136 + g) * 32 + c0];
                uint32_t l1 = w[(136 + g) * 32 + c1];
                mma_tf32(acc[0][8], af[0], b0, b1);
                mma_tf32(acc[1][8], af[1], b0, b1);
                mma_tf32(acc[0][8], af[0], l0, l1);
                mma_tf32(acc[1][8], af[1], l0, l1);
                mma_tf32(acc[0][8], alo[0], b0, b1);
                mma_tf32(acc[1][8], alo[1], b0, b1);
            }
        }
    }

    // ---- epilogue: router softmax -> top2 -> renorm gates ----
    if (wn == 1) {
        const float rb0 = rb[2 * tig];
        const float rb1 = rb[2 * tig + 1];
#pragma unroll
        for (int mt = 0; mt < 2; ++mt) {
#pragma unroll
            for (int half = 0; half < 2; ++half) {
                float l0 = acc[mt][8][half * 2 + 0] + rb0;
                float l1 = acc[mt][8][half * 2 + 1] + rb1;
                float m1, m2; int i1, i2;
                if (l0 >= l1) { m1 = l0; i1 = 2 * tig;     m2 = l1; i2 = 2 * tig + 1; }
                else          { m1 = l1; i1 = 2 * tig + 1; m2 = l0; i2 = 2 * tig; }
#pragma unroll
                for (int d = 1; d <= 2; d <<= 1) {
                    float om1 = __shfl_xor_sync(0xffffffffu, m1, d);
                    int   oi1 = __shfl_xor_sync(0xffffffffu, i1, d);
                    float om2 = __shfl_xor_sync(0xffffffffu, m2, d);
                    int   oi2 = __shfl_xor_sync(0xffffffffu, i2, d);
                    if (om1 > m1) {
                        if (m1 >= om2) { m2 = m1; i2 = i1; }
                        else           { m2 = om2; i2 = oi2; }
                        m1 = om1; i1 = oi1;
                    } else if (om1 > m2) { m2 = om1; i2 = oi1; }
                }
                float g1 = 1.f / (1.f + __expf(m2 - m1));
                float g2 = 1.f - g1;
                int row = wm * 32 + mt * 16 + half * 8 + g;
                gw[row * 8 + 2 * tig]     = (2 * tig     == i1) ? g1 : ((2 * tig     == i2) ? g2 : 0.f);
                gw[row * 8 + 2 * tig + 1] = (2 * tig + 1 == i1) ? g1 : ((2 * tig + 1 == i2) ? g2 : 0.f);
            }
        }
    }
    __syncthreads();

    // ---- gate h and store pre-rounded tf32 hw ----
#pragma unroll
    for (int mt = 0; mt < 2; ++mt) {
#pragma unroll
        for (int nt = 0; nt < 8; ++nt) {
            const int col = ncol0 + nt * 8 + 2 * tig;   // 0..127
            const int e  = col >> 4;
            const int ra = wm * 32 + mt * 16 + g;
            const int rbw = ra + 8;
            const float wa = gw[ra * 8 + e];
            const float wb = gw[rbw * 8 + e];
            uint2 va = make_uint2(f2tf(acc[mt][nt][0] * wa), f2tf(acc[mt][nt][1] * wa));
            uint2 vb = make_uint2(f2tf(acc[mt][nt][2] * wb), f2tf(acc[mt][nt][3] * wb));
            *(uint2*)(g_hw + (size_t)(m0 + ra)  * 128 + col) = va;
            *(uint2*)(g_hw + (size_t)(m0 + rbw) * 128 + col) = vb;
        }
    }
}

// ============================================================================
// GEMM2: out[N,4096] = hw @ Bt^T. Persistent per-n-block: Bt tile resident,
// double-buffered cp.async hw sweep over 32 m-tiles. Zero cvt in hot loop.
// SMEM: Bs[128][128] + Hs[2][128][128]  (192 KB)
// ============================================================================
#define SM2_WORDS (128 * 128 + 2 * 128 * 128)

__global__ __launch_bounds__(256, 1)
void gemm2_kernel(float* __restrict__ out)
{
    extern __shared__ uint32_t smu[];
    uint32_t* Bs = smu;               // [128][128]
    uint32_t* Hs = smu + 128 * 128;   // [2][128][128]

    const int tid  = threadIdx.x;
    const int lane = tid & 31;
    const int warp = tid >> 5;
    const int wm   = warp & 3;
    const int wn   = warp >> 2;
    const int g    = lane >> 2;
    const int tig  = lane & 3;
    const int n0   = (blockIdx.x & 31) * 128;
    const int mc   = blockIdx.x >> 5;       // 0..3, 32 m-tiles each

    // ---- Bs once ----
#pragma unroll
    for (int i = 0; i < 16; i++) {
        int idx = tid + i * 256, row = idx >> 5, c4 = idx & 31;
        int col = (4 * c4) ^ ((row & 7) * 4);
        cp16(Bs + row * 128 + col, g_bt + (size_t)(n0 + row) * 128 + 4 * c4);
    }
    CP_COMMIT();

    auto issueH = [&](int stage, int it) {
        const int m0 = (mc * 32 + it) * 128;
#pragma unroll
        for (int i = 0; i < 16; i++) {
            int idx = tid + i * 256, row = idx >> 5, c4 = idx & 31;
            int col = (4 * c4) ^ ((row & 7) * 4);
            cp16(Hs + stage * 16384 + row * 128 + col,
                 g_hw + (size_t)(m0 + row) * 128 + 4 * c4);
        }
    };
    issueH(0, 0); CP_COMMIT();

    for (int it = 0; it < 32; ++it) {
        __syncthreads();                       // all warps done with buf (it+1)&1
        if (it + 1 < 32) issueH((it + 1) & 1, it + 1);
        CP_COMMIT();
        CP_WAIT(1);                            // stage it landed
        __syncthreads();

        const uint32_t* hs = Hs + (it & 1) * 16384;
        float acc[2][8][4];
#pragma unroll
        for (int mt = 0; mt < 2; mt++)
#pragma unroll
            for (int nt = 0; nt < 8; nt++)
#pragma unroll
                for (int i = 0; i < 4; i++) acc[mt][nt][i] = 0.f;

#pragma unroll
        for (int ks = 0; ks < 16; ++ks) {
            const int k = ks * 8;
            const int c0 = (k + tig)     ^ (g * 4);
            const int c1 = (k + tig + 4) ^ (g * 4);
            uint32_t af[2][4];
#pragma unroll
            for (int mt = 0; mt < 2; ++mt) {
                const int r0 = wm * 32 + mt * 16 + g;
                af[mt][0] = hs[r0 * 128 + c0];
                af[mt][1] = hs[(r0 + 8) * 128 + c0];
                af[mt][2] = hs[r0 * 128 + c1];
                af[mt][3] = hs[(r0 + 8) * 128 + c1];
            }
#pragma unroll
            for (int nt = 0; nt < 8; ++nt) {
                const int n = wn * 64 + nt * 8 + g;    // n&7 == g
                uint32_t b0 = Bs[n * 128 + c0];
                uint32_t b1 = Bs[n * 128 + c1];
                mma_tf32(acc[0][nt], af[0], b0, b1);
                mma_tf32(acc[1][nt], af[1], b0, b1);
            }
        }

        const int m0 = (mc * 32 + it) * 128;
#pragma unroll
        for (int mt = 0; mt < 2; ++mt) {
#pragma unroll
            for (int nt = 0; nt < 8; ++nt) {
                const int col = n0 + wn * 64 + nt * 8 + 2 * tig;
                const int ra  = m0 + wm * 32 + mt * 16 + g;
                *(float2*)(out + (size_t)ra * OUT_D + col) =
                    make_float2(acc[mt][nt][0], acc[mt][nt][1]);
                *(float2*)(out + (size_t)(ra + 8) * OUT_D + col) =
                    make_float2(acc[mt][nt][2], acc[mt][nt][3]);
            }
        }
    }
}

// ============================================================================
extern "C" void kernel_launch(void* const* d_in, const int* in_sizes, int n_in,
                              void* d_out, int out_size)
{
    const float* x  = (const float*)d_in[0];   // [N, 4096]
    const float* rw = (const float*)d_in[1];   // [8, 4096]
    const float* rb = (const float*)d_in[2];   // [8]
    const float* A  = (const float*)d_in[3];   // [8,16,4096]
    const float* Bm = (const float*)d_in[4];   // [8,4096,16]
    float* out = (float*)d_out;                // [N, 4096] fp32

    const int sm1 = SM1_WORDS * 4;   // 143360 B
    const int sm2 = SM2_WORDS * 4;   // 196608 B
    cudaFuncSetAttribute(gemm1_kernel,
                         cudaFuncAttributeMaxDynamicSharedMemorySize, sm1);
    cudaFuncSetAttribute(gemm2_kernel,
                         cudaFuncAttributeMaxDynamicSharedMemorySize, sm2);

    prep_kernel<<<1024, 256>>>(rw, A, Bm);
    gemm1_kernel<<<N_TOK / 128, 256, sm1>>>(x, rb);
    gemm2_kernel<<<128, 256, sm2>>>(out);
}

// round 5
// speedup vs baseline: 1.2565x; 1.0243x over previous
#include <cuda_runtime.h>
#include <cstdint>
#include <cstddef>

// Problem constants: B=4, S=4096 -> N=16384 tokens
#define N_TOK 16384
#define DIM   4096
#define OUT_D 4096
#define SCALING 0.5f
#define W1_N8 18   // 144 rows / 8: 16 A-blocks + router-hi + router-lo

// -------- static scratch, all in mma-fragment-major order --------
// g_w1f: [k8 0..511][n8 0..17][lane 0..31][2]   (B-frag for GEMM1)
//   rows 0-127 = A (tf32), 128-135 router hi, 136-143 router lo
__device__ __align__(16) uint32_t g_w1f[512 * W1_N8 * 64];
// g_btf: [n8 0..511][k8 0..15][lane][2]          (B-frag for GEMM2)
__device__ __align__(16) uint32_t g_btf[512 * 16 * 64];
// g_hwf: [m16 0..1023][k8 0..15][lane][4]        (A-frag for GEMM2, tf32)
__device__ __align__(16) uint32_t g_hwf[(size_t)1024 * 16 * 128];

// -------- helpers --------
__device__ __forceinline__ uint32_t f2tf(float f) {
    uint32_t u;
    asm("cvt.rna.tf32.f32 %0, %1;" : "=r"(u) : "f"(f));
    return u;
}

__device__ __forceinline__ void mma_tf32(float* c, const uint32_t* a,
                                         uint32_t b0, uint32_t b1) {
    asm volatile(
        "mma.sync.aligned.m16n8k8.row.col.f32.tf32.tf32.f32 "
        "{%0,%1,%2,%3}, {%4,%5,%6,%7}, {%8,%9}, {%0,%1,%2,%3};\n"
        : "+f"(c[0]), "+f"(c[1]), "+f"(c[2]), "+f"(c[3])
        : "r"(a[0]), "r"(a[1]), "r"(a[2]), "r"(a[3]), "r"(b0), "r"(b1));
}

__device__ __forceinline__ void cp16(void* dst, const void* src) {
    uint32_t d = (uint32_t)__cvta_generic_to_shared(dst);
    asm volatile("cp.async.cg.shared.global [%0], [%1], 16;" :: "r"(d), "l"(src));
}
#define CP_COMMIT() asm volatile("cp.async.commit_group;")
#define CP_WAIT(n)  asm volatile("cp.async.wait_group %0;" :: "n"(n))

// B-frag word index for matrix element (row n, col k) of a col-major B operand:
// block (n>>3, k>>3), lane = (n&7)*4 + (k&3), word j = (k>>2)&1.
__device__ __forceinline__ int bfrag_idx(int n, int k, int nblocks_per_k8) {
    return ((k >> 3) * nblocks_per_k8 + (n >> 3)) * 64
         + ((n & 7) * 4 + (k & 3)) * 2 + ((k >> 2) & 1);
}

// ============================================================================
// Prep: build fragment-major tf32 operand tensors once.
// ============================================================================
__global__ void prep_kernel(const float* __restrict__ rw,
                            const float* __restrict__ A,
                            const float* __restrict__ Bm)
{
    const int nthr = gridDim.x * blockDim.x;
    const int tid0 = blockIdx.x * blockDim.x + threadIdx.x;
    // W1 (GEMM1 B operand): [k8][n8][lane][2]
    for (int i = tid0; i < 144 * 4096; i += nthr) {
        int n = i >> 12, k = i & 4095;
        uint32_t v;
        if (n < 128)      v = f2tf(A[i]);
        else if (n < 136) v = f2tf(rw[(n - 128) * 4096 + k]);
        else {
            float f = rw[(n - 136) * 4096 + k];
            uint32_t hi = f2tf(f);
            v = f2tf(f - __uint_as_float(hi));
        }
        g_w1f[bfrag_idx(n, k, W1_N8)] = v;
    }
    // Bt (GEMM2 B operand): [n8][k8][lane][2]  (note n8-major here)
    for (int i = tid0; i < 4096 * 128; i += nthr) {
        int o = i >> 7, c = i & 127, e = c >> 4, r = c & 15;
        uint32_t v = f2tf(Bm[((size_t)e * 4096 + o) * 16 + r] * SCALING);
        int idx = ((o >> 3) * 16 + (c >> 3)) * 64
                + ((o & 7) * 4 + (c & 3)) * 2 + ((c >> 2) & 1);
        g_btf[idx] = v;
    }
}

// ============================================================================
// GEMM1: C[N,144] = X @ W1^T, compensated-tf32 logits (alternating wn by
// k-tile parity), fused gating, hw stored fragment-major to g_hwf.
// SMEM: As[4][128][32] raw x (swizzled) + Ws[4][4*18*64] frag + gw + lbuf
// ============================================================================
#define AS_WORDS (4 * 128 * 32)         // 16384
#define WS_WORDS (4 * 4 * W1_N8 * 64)   // 18432
#define SM1_WORDS (AS_WORDS + WS_WORDS + 1024 + 1024)

__global__ __launch_bounds__(256, 1)
void gemm1_kernel(const float* __restrict__ x, const float* __restrict__ rb)
{
    extern __shared__ uint32_t smu[];
    uint32_t* As   = smu;
    uint32_t* Ws   = smu + AS_WORDS;
    float*    gw   = (float*)(smu + AS_WORDS + WS_WORDS);          // [128][8]
    float*    lbuf = (float*)(smu + AS_WORDS + WS_WORDS + 1024);   // [4][2][32][4]

    const int tid  = threadIdx.x;
    const int lane = tid & 31;
    const int warp = tid >> 5;
    const int wm   = warp & 3;
    const int wn   = warp >> 2;
    const int g    = lane >> 2;
    const int tig  = lane & 3;
    const int m0   = blockIdx.x * 128;
    const int ncol0 = wn * 64;

    float acc[2][9][4];
#pragma unroll
    for (int mt = 0; mt < 2; mt++)
#pragma unroll
        for (int nt = 0; nt < 9; nt++)
#pragma unroll
            for (int i = 0; i < 4; i++) acc[mt][nt][i] = 0.f;

    auto issue = [&](int stage, int t) {
        const int k0 = t * 32;
        uint32_t* ab = As + stage * 128 * 32;
        uint32_t* wb = Ws + stage * 4 * W1_N8 * 64;
#pragma unroll
        for (int i = 0; i < 4; i++) {
            int idx = tid + i * 256, row = idx >> 3, c4 = idx & 7;
            int col = (4 * c4) ^ ((row & 7) * 4);
            cp16(ab + row * 32 + col, x + (size_t)(m0 + row) * DIM + k0 + 4 * c4);
        }
        // W frag tile for k8 = 4t..4t+3 is contiguous: 4*18*64 = 4608 words
#pragma unroll
        for (int i = 0; i < 5; i++) {
            int idx = tid + i * 256;
            if (idx < 1152)
                cp16(wb + idx * 4, g_w1f + (size_t)t * 4608 + idx * 4);
        }
    };

    issue(0, 0); CP_COMMIT();
    issue(1, 1); CP_COMMIT();
    issue(2, 2); CP_COMMIT();

    const int T = DIM / 32;   // 128
    for (int t = 0; t < T; ++t) {
        CP_WAIT(2);
        __syncthreads();
        if (t + 3 < T) issue((t + 3) & 3, t + 3);
        CP_COMMIT();

        const uint32_t* a = As + (t & 3) * 128 * 32;
        const uint32_t* w = Ws + (t & 3) * 4 * W1_N8 * 64;
        const bool do_logits = (wn == (t & 1));   // balanced across wn groups
#pragma unroll
        for (int ks = 0; ks < 4; ++ks) {
            const int k = ks * 8;
            const int c0 = (k + tig)     ^ (g * 4);
            const int c1 = (k + tig + 4) ^ (g * 4);
            uint32_t af[2][4];
            float raw[2][4];
#pragma unroll
            for (int mt = 0; mt < 2; ++mt) {
                const int r0 = wm * 32 + mt * 16 + g;
                raw[mt][0] = __uint_as_float(a[r0 * 32 + c0]);
                raw[mt][1] = __uint_as_float(a[(r0 + 8) * 32 + c0]);
                raw[mt][2] = __uint_as_float(a[r0 * 32 + c1]);
                raw[mt][3] = __uint_as_float(a[(r0 + 8) * 32 + c1]);
#pragma unroll
                for (int j = 0; j < 4; j++) af[mt][j] = f2tf(raw[mt][j]);
            }
#pragma unroll
            for (int nt = 0; nt < 8; ++nt) {
                const int n8 = wn * 8 + nt;
                uint2 bb = *(const uint2*)(w + (ks * W1_N8 + n8) * 64 + lane * 2);
                mma_tf32(acc[0][nt], af[0], bb.x, bb.y);
                mma_tf32(acc[1][nt], af[1], bb.x, bb.y);
            }
            if (do_logits) {
                uint32_t alo[2][4];
#pragma unroll
                for (int mt = 0; mt < 2; ++mt)
#pragma unroll
                    for (int j = 0; j < 4; j++)
                        alo[mt][j] = f2tf(raw[mt][j] - __uint_as_float(af[mt][j]));
                uint2 bh = *(const uint2*)(w + (ks * W1_N8 + 16) * 64 + lane * 2);
                uint2 bl = *(const uint2*)(w + (ks * W1_N8 + 17) * 64 + lane * 2);
                mma_tf32(acc[0][8], af[0], bh.x, bh.y);
                mma_tf32(acc[1][8], af[1], bh.x, bh.y);
                mma_tf32(acc[0][8], af[0], bl.x, bl.y);
                mma_tf32(acc[1][8], af[1], bl.x, bl.y);
                mma_tf32(acc[0][8], alo[0], bh.x, bh.y);
                mma_tf32(acc[1][8], alo[1], bh.x, bh.y);
            }
        }
    }

    // ---- combine partial logits: wn0 -> SMEM, wn1 adds ----
    if (wn == 0) {
#pragma unroll
        for (int mt = 0; mt < 2; ++mt)
#pragma unroll
            for (int j = 0; j < 4; ++j)
                lbuf[((wm * 2 + mt) * 32 + lane) * 4 + j] = acc[mt][8][j];
    }
    __syncthreads();

    // ---- epilogue: router softmax -> top2 -> renorm gates (wn==1) ----
    if (wn == 1) {
        const float rb0 = rb[2 * tig];
        const float rb1 = rb[2 * tig + 1];
#pragma unroll
        for (int mt = 0; mt < 2; ++mt) {
#pragma unroll
            for (int j = 0; j < 4; ++j)
                acc[mt][8][j] += lbuf[((wm * 2 + mt) * 32 + lane) * 4 + j];
#pragma unroll
            for (int half = 0; half < 2; ++half) {
                float l0 = acc[mt][8][half * 2 + 0] + rb0;
                float l1 = acc[mt][8][half * 2 + 1] + rb1;
                float m1, m2; int i1, i2;
                if (l0 >= l1) { m1 = l0; i1 = 2 * tig;     m2 = l1; i2 = 2 * tig + 1; }
                else          { m1 = l1; i1 = 2 * tig + 1; m2 = l0; i2 = 2 * tig; }
#pragma unroll
                for (int d = 1; d <= 2; d <<= 1) {
                    float om1 = __shfl_xor_sync(0xffffffffu, m1, d);
                    int   oi1 = __shfl_xor_sync(0xffffffffu, i1, d);
                    float om2 = __shfl_xor_sync(0xffffffffu, m2, d);
                    int   oi2 = __shfl_xor_sync(0xffffffffu, i2, d);
                    if (om1 > m1) {
                        if (m1 >= om2) { m2 = m1; i2 = i1; }
                        else           { m2 = om2; i2 = oi2; }
                        m1 = om1; i1 = oi1;
                    } else if (om1 > m2) { m2 = om1; i2 = oi1; }
                }
                float g1 = 1.f / (1.f + __expf(m2 - m1));
                float g2 = 1.f - g1;
                int row = wm * 32 + mt * 16 + half * 8 + g;
                gw[row * 8 + 2 * tig]     = (2 * tig     == i1) ? g1 : ((2 * tig     == i2) ? g2 : 0.f);
                gw[row * 8 + 2 * tig + 1] = (2 * tig + 1 == i1) ? g1 : ((2 * tig + 1 == i2) ? g2 : 0.f);
            }
        }
    }
    __syncthreads();

    // ---- gate h, store to g_hwf in A-fragment-major order ----
    // value (r,c) within (m16,k8) block -> word (lane'= (r&7)*4+(c&3))*4
    //                                     + j = (c>>2)*2 + (r>>3)
#pragma unroll
    for (int mt = 0; mt < 2; ++mt) {
#pragma unroll
        for (int nt = 0; nt < 8; ++nt) {
            const int col = ncol0 + nt * 8 + 2 * tig;
            const int e  = col >> 4;
            const int ra = wm * 32 + mt * 16 + g;
            const float wa = gw[ra * 8 + e];
            const float wb = gw[(ra + 8) * 8 + e];
            const int m16 = (m0 + wm * 32 + mt * 16) >> 4;
            const int k8  = wn * 8 + nt;
            uint32_t* base = g_hwf + ((size_t)m16 * 16 + k8) * 128;
            // idx00: (r=g, c=2tig) -> pairs with (r=g+8, c=2tig) at +1
            const int idx00 = (g * 4 + ((2 * tig) & 3)) * 4 + (tig >> 1) * 2;
            *(uint2*)(base + idx00) =
                make_uint2(f2tf(acc[mt][nt][0] * wa), f2tf(acc[mt][nt][2] * wb));
            *(uint2*)(base + idx00 + 4) =
                make_uint2(f2tf(acc[mt][nt][1] * wa), f2tf(acc[mt][nt][3] * wb));
        }
    }
}

// ============================================================================
// GEMM2: out[N,4096] = hw @ Bt^T.  Block 256m x 128n, 8 warps of 64x64.
// B resident in SMEM (frag-major, LDS.64); A-frags LDG.128 straight from
// L2-resident g_hwf. No syncthreads in the m-sweep.
// ============================================================================
#define SM2_WORDS (16 * 16 * 64)    // 16384 words = 64 KB

__global__ __launch_bounds__(256, 1)
void gemm2_kernel(float* __restrict__ out)
{
    extern __shared__ uint32_t smu[];
    uint32_t* Bs = smu;   // [16 n8][16 k8][64]

    const int tid  = threadIdx.x;
    const int lane = tid & 31;
    const int warp = tid >> 5;
    const int wm   = warp & 3;        // 4 m-groups of 64 rows
    const int wn   = warp >> 2;       // 2 n-groups of 64 cols
    const int nb   = blockIdx.x & 31; // n-block (128 cols)
    const int mc   = blockIdx.x >> 5; // 0..3, 16 m-tiles (256 rows) each

    // ---- Bs once: contiguous 16384-word slab of g_btf ----
#pragma unroll
    for (int i = 0; i < 16; i++) {
        int idx = tid + i * 256;
        cp16(Bs + idx * 4, g_btf + (size_t)nb * 16384 + idx * 4);
    }
    CP_COMMIT(); CP_WAIT(0);
    __syncthreads();

    const int n0 = nb * 128;
    for (int it = 0; it < 16; ++it) {
        const int mbase = (mc * 16 + it) * 256;
        const int m16b  = (mbase >> 4) + wm * 4;   // first m16 block for this warp

        float acc[4][8][4];
#pragma unroll
        for (int mt = 0; mt < 4; mt++)
#pragma unroll
            for (int nt = 0; nt < 8; nt++)
#pragma unroll
                for (int i = 0; i < 4; i++) acc[mt][nt][i] = 0.f;

        uint4 af[4];
#pragma unroll
        for (int mt = 0; mt < 4; mt++)
            af[mt] = *(const uint4*)(g_hwf + ((size_t)(m16b + mt) * 16 + 0) * 128 + lane * 4);

#pragma unroll
        for (int ks = 0; ks < 16; ++ks) {
            uint4 afn[4];
            if (ks < 15) {
#pragma unroll
                for (int mt = 0; mt < 4; mt++)
                    afn[mt] = *(const uint4*)(g_hwf + ((size_t)(m16b + mt) * 16 + ks + 1) * 128 + lane * 4);
            }
            uint2 bf[8];
#pragma unroll
            for (int nt = 0; nt < 8; nt++) {
                const int n8l = wn * 8 + nt;
                bf[nt] = *(const uint2*)(Bs + (n8l * 16 + ks) * 64 + lane * 2);
            }
#pragma unroll
            for (int nt = 0; nt < 8; nt++)
#pragma unroll
                for (int mt = 0; mt < 4; mt++)
                    mma_tf32(acc[mt][nt], (const uint32_t*)&af[mt], bf[nt].x, bf[nt].y);
            if (ks < 15) {
#pragma unroll
                for (int mt = 0; mt < 4; mt++) af[mt] = afn[mt];
            }
        }

        const int g   = lane >> 2;
        const int tig = lane & 3;
#pragma unroll
        for (int mt = 0; mt < 4; ++mt) {
#pragma unroll
            for (int nt = 0; nt < 8; ++nt) {
                const int col = n0 + wn * 64 + nt * 8 + 2 * tig;
                const int ra  = mbase + wm * 64 + mt * 16 + g;
                *(float2*)(out + (size_t)ra * OUT_D + col) =
                    make_float2(acc[mt][nt][0], acc[mt][nt][1]);
                *(float2*)(out + (size_t)(ra + 8) * OUT_D + col) =
                    make_float2(acc[mt][nt][2], acc[mt][nt][3]);
            }
        }
    }
}

// ============================================================================
extern "C" void kernel_launch(void* const* d_in, const int* in_sizes, int n_in,
                              void* d_out, int out_size)
{
    const float* x  = (const float*)d_in[0];   // [N, 4096]
    const float* rw = (const float*)d_in[1];   // [8, 4096]
    const float* rb = (const float*)d_in[2];   // [8]
    const float* A  = (const float*)d_in[3];   // [8,16,4096]
    const float* Bm = (const float*)d_in[4];   // [8,4096,16]
    float* out = (float*)d_out;                // [N, 4096] fp32

    const int sm1 = SM1_WORDS * 4;   // 147456 B
    const int sm2 = SM2_WORDS * 4;   // 65536 B
    cudaFuncSetAttribute(gemm1_kernel,
                         cudaFuncAttributeMaxDynamicSharedMemorySize, sm1);
    cudaFuncSetAttribute(gemm2_kernel,
                         cudaFuncAttributeMaxDynamicSharedMemorySize, sm2);

    prep_kernel<<<1024, 256>>>(rw, A, Bm);
    gemm1_kernel<<<N_TOK / 128, 256, sm1>>>(x, rb);
    gemm2_kernel<<<128, 256, sm2>>>(out);
}

// round 7
// speedup vs baseline: 1.8681x; 1.4867x over previous
#include <cuda_runtime.h>
#include <cuda_fp16.h>
#include <cstdint>
#include <cstddef>

// Problem constants: B=4, S=4096 -> N=16384 tokens
#define N_TOK 16384
#define DIM   4096
#define OUT_D 4096
#define SCALING 0.5f
#define W1_N8 18   // 144 rows / 8: 16 A-blocks + router-hi + router-lo

// -------- static scratch, fp16 fragment-major (m16n8k16) --------
// GEMM1 B operand: [k16 0..255][n8 0..17][lane*2 + reg]  (reg=(k>>3)&1)
__device__ __align__(16) uint32_t g_w1f[256 * W1_N8 * 64];
// GEMM2 B operand: [n8 0..511][k16 0..7][lane*2 + reg]
__device__ __align__(16) uint32_t g_btf[512 * 8 * 64];
// GEMM2 A operand: [m16 0..1023][k16 0..7][lane*4 + reg]
__device__ __align__(16) uint32_t g_hwf[(size_t)1024 * 8 * 128];

// -------- helpers --------
__device__ __forceinline__ uint32_t pack_f16x2(float lo, float hi) {
    uint32_t r;   // d.low = 2nd src, d.high = 1st src
    asm("cvt.rn.f16x2.f32 %0, %1, %2;" : "=r"(r) : "f"(hi), "f"(lo));
    return r;
}
__device__ __forceinline__ float2 unpack_f16x2(uint32_t v) {
    __half2 h = *(__half2*)&v;
    return __half22float2(h);
}
__device__ __forceinline__ void mma_f16(float* c, const uint32_t* a,
                                        uint32_t b0, uint32_t b1) {
    asm volatile(
        "mma.sync.aligned.m16n8k16.row.col.f32.f16.f16.f32 "
        "{%0,%1,%2,%3}, {%4,%5,%6,%7}, {%8,%9}, {%0,%1,%2,%3};\n"
        : "+f"(c[0]), "+f"(c[1]), "+f"(c[2]), "+f"(c[3])
        : "r"(a[0]), "r"(a[1]), "r"(a[2]), "r"(a[3]), "r"(b0), "r"(b1));
}
__device__ __forceinline__ void cp16(void* dst, const void* src) {
    uint32_t d = (uint32_t)__cvta_generic_to_shared(dst);
    asm volatile("cp.async.cg.shared.global [%0], [%1], 16;" :: "r"(d), "l"(src));
}
#define CP_COMMIT() asm volatile("cp.async.commit_group;")
#define CP_WAIT(n)  asm volatile("cp.async.wait_group %0;" :: "n"(n))

// ============================================================================
// Prep: build fp16 fragment-major operand tensors once.
// B-frag map (col-major n8 x k16): lane=(n&7)*4+((k&7)>>1), reg=(k>>3)&1, half=k&1
// A-frag map (row-major m16 x k16): lane=(r&7)*4+((c&7)>>1), reg=(r>>3)+2*(c>>3)
// ============================================================================
__global__ void prep_kernel(const float* __restrict__ rw,
                            const float* __restrict__ A,
                            const float* __restrict__ Bm)
{
    const int nthr = gridDim.x * blockDim.x;
    const int tid0 = blockIdx.x * blockDim.x + threadIdx.x;
    // W1: rows 0-127 A, 128-135 router hi, 136-143 router lo residual
    for (int i = tid0; i < 144 * 2048; i += nthr) {
        int n = i >> 11, k = (i & 2047) * 2;
        float v0, v1;
        if (n < 128) {
            v0 = A[n * 4096 + k]; v1 = A[n * 4096 + k + 1];
        } else if (n < 136) {
            v0 = rw[(n - 128) * 4096 + k]; v1 = rw[(n - 128) * 4096 + k + 1];
        } else {
            float f0 = rw[(n - 136) * 4096 + k];
            float f1 = rw[(n - 136) * 4096 + k + 1];
            v0 = f0 - __half2float(__float2half_rn(f0));
            v1 = f1 - __half2float(__float2half_rn(f1));
        }
        int idx = ((k >> 4) * W1_N8 + (n >> 3)) * 64
                + ((n & 7) * 4 + ((k & 7) >> 1)) * 2 + ((k >> 3) & 1);
        g_w1f[idx] = pack_f16x2(v0, v1);
    }
    // Bt: element (o, c): Bm[e][o][r]*SCALING, c = e*16+r
    for (int i = tid0; i < 4096 * 64; i += nthr) {
        int o = i >> 6, c = (i & 63) * 2;
        int e = c >> 4, r = c & 15;
        const float* bp = Bm + ((size_t)e * 4096 + o) * 16 + r;
        int idx = ((o >> 3) * 8 + (c >> 4)) * 64
                + ((o & 7) * 4 + ((c & 7) >> 1)) * 2 + ((c >> 3) & 1);
        g_btf[idx] = pack_f16x2(bp[0] * SCALING, bp[1] * SCALING);
    }
}

// ============================================================================
// GEMM1: C[N,144] = X @ W1^T (fp16 mma, compensated logits), fused gating,
// hw emitted directly in GEMM2 A-fragment order.
// SMEM: As[4][128][32] raw x (xor-swizzled) + Ws[4][2*18*64] frags + gw + lbuf
// ============================================================================
#define AS_WORDS (4 * 128 * 32)          // 16384
#define WS_STAGE (2 * W1_N8 * 64)        // 2304
#define WS_WORDS (4 * WS_STAGE)          // 9216
#define SM1_WORDS (AS_WORDS + WS_WORDS + 1024 + 1024)

__global__ __launch_bounds__(256, 1)
void gemm1_kernel(const float* __restrict__ x, const float* __restrict__ rb)
{
    extern __shared__ uint32_t smu[];
    uint32_t* As   = smu;
    uint32_t* Ws   = smu + AS_WORDS;
    float*    gw   = (float*)(smu + AS_WORDS + WS_WORDS);          // [128][8]
    float*    lbuf = (float*)(smu + AS_WORDS + WS_WORDS + 1024);   // [8][32][4]

    const int tid  = threadIdx.x;
    const int lane = tid & 31;
    const int warp = tid >> 5;
    const int wm   = warp & 3;
    const int wn   = warp >> 2;
    const int g    = lane >> 2;
    const int tig  = lane & 3;
    const int m0   = blockIdx.x * 128;
    const int ncol0 = wn * 64;

    float acc[2][9][4];
#pragma unroll
    for (int mt = 0; mt < 2; mt++)
#pragma unroll
        for (int nt = 0; nt < 9; nt++)
#pragma unroll
            for (int i = 0; i < 4; i++) acc[mt][nt][i] = 0.f;

    auto issue = [&](int stage, int t) {
        const int k0 = t * 32;
        uint32_t* ab = As + stage * 128 * 32;
        uint32_t* wb = Ws + stage * WS_STAGE;
#pragma unroll
        for (int i = 0; i < 4; i++) {
            int idx = tid + i * 256, row = idx >> 3, c4 = idx & 7;
            int col = (4 * c4) ^ ((row & 7) * 4);
            cp16(ab + row * 32 + col, x + (size_t)(m0 + row) * DIM + k0 + 4 * c4);
        }
        // W frag slab for this k32 tile: 2304 words = 576 uint4, contiguous
#pragma unroll
        for (int i = 0; i < 3; i++) {
            int idx = tid + i * 256;
            if (idx < 576)
                cp16(wb + idx * 4, g_w1f + (size_t)t * WS_STAGE + idx * 4);
        }
    };

    issue(0, 0); CP_COMMIT();
    issue(1, 1); CP_COMMIT();
    issue(2, 2); CP_COMMIT();

    const int T = DIM / 32;   // 128
    for (int t = 0; t < T; ++t) {
        CP_WAIT(2);
        __syncthreads();
        if (t + 3 < T) issue((t + 3) & 3, t + 3);
        CP_COMMIT();

        const uint32_t* a = As + (t & 3) * 128 * 32;
        const uint32_t* w = Ws + (t & 3) * WS_STAGE;
        const bool do_logits = (wn == (t & 1));
#pragma unroll
        for (int ks = 0; ks < 2; ++ks) {
            const int k = ks * 16;
            uint32_t af[2][4];
            float2 raw[2][4];
#pragma unroll
            for (int mt = 0; mt < 2; ++mt) {
                const int r0 = wm * 32 + mt * 16 + g;
                const int clo = k + 2 * tig, chi = k + 8 + 2 * tig;
                // swizzled SMEM address of (row r, col c), c even
                const int alo0 = r0 * 32 + (((clo & ~3) ^ ((r0 & 7) * 4)) | (clo & 3));
                const int alo1 = (r0 + 8) * 32 + (((clo & ~3) ^ (((r0 + 8) & 7) * 4)) | (clo & 3));
                const int ahi0 = r0 * 32 + (((chi & ~3) ^ ((r0 & 7) * 4)) | (chi & 3));
                const int ahi1 = (r0 + 8) * 32 + (((chi & ~3) ^ (((r0 + 8) & 7) * 4)) | (chi & 3));
                raw[mt][0] = *(const float2*)(a + alo0);
                raw[mt][1] = *(const float2*)(a + alo1);
                raw[mt][2] = *(const float2*)(a + ahi0);
                raw[mt][3] = *(const float2*)(a + ahi1);
#pragma unroll
                for (int j = 0; j < 4; j++)
                    af[mt][j] = pack_f16x2(raw[mt][j].x, raw[mt][j].y);
            }
#pragma unroll
            for (int nt = 0; nt < 8; ++nt) {
                const int n8 = wn * 8 + nt;
                uint2 bb = *(const uint2*)(w + (ks * W1_N8 + n8) * 64 + lane * 2);
                mma_f16(acc[0][nt], af[0], bb.x, bb.y);
                mma_f16(acc[1][nt], af[1], bb.x, bb.y);
            }
            if (do_logits) {
                uint32_t alo[2][4];
#pragma unroll
                for (int mt = 0; mt < 2; ++mt)
#pragma unroll
                    for (int j = 0; j < 4; j++) {
                        float2 hv = unpack_f16x2(af[mt][j]);
                        alo[mt][j] = pack_f16x2(raw[mt][j].x - hv.x,
                                                raw[mt][j].y - hv.y);
                    }
                uint2 bh = *(const uint2*)(w + (ks * W1_N8 + 16) * 64 + lane * 2);
                uint2 bl = *(const uint2*)(w + (ks * W1_N8 + 17) * 64 + lane * 2);
                mma_f16(acc[0][8], af[0], bh.x, bh.y);
                mma_f16(acc[1][8], af[1], bh.x, bh.y);
                mma_f16(acc[0][8], af[0], bl.x, bl.y);
                mma_f16(acc[1][8], af[1], bl.x, bl.y);
                mma_f16(acc[0][8], alo[0], bh.x, bh.y);
                mma_f16(acc[1][8], alo[1], bh.x, bh.y);
            }
        }
    }

    // ---- combine partial logits: wn0 -> SMEM, wn1 adds ----
    if (wn == 0) {
#pragma unroll
        for (int mt = 0; mt < 2; ++mt)
#pragma unroll
            for (int j = 0; j < 4; ++j)
                lbuf[((wm * 2 + mt) * 32 + lane) * 4 + j] = acc[mt][8][j];
    }
    __syncthreads();

    // ---- epilogue: router softmax -> top2 -> renorm gates (wn==1) ----
    if (wn == 1) {
        const float rb0 = rb[2 * tig];
        const float rb1 = rb[2 * tig + 1];
#pragma unroll
        for (int mt = 0; mt < 2; ++mt) {
#pragma unroll
            for (int j = 0; j < 4; ++j)
                acc[mt][8][j] += lbuf[((wm * 2 + mt) * 32 + lane) * 4 + j];
#pragma unroll
            for (int half = 0; half < 2; ++half) {
                float l0 = acc[mt][8][half * 2 + 0] + rb0;
                float l1 = acc[mt][8][half * 2 + 1] + rb1;
                float m1, m2; int i1, i2;
                if (l0 >= l1) { m1 = l0; i1 = 2 * tig;     m2 = l1; i2 = 2 * tig + 1; }
                else          { m1 = l1; i1 = 2 * tig + 1; m2 = l0; i2 = 2 * tig; }
#pragma unroll
                for (int d = 1; d <= 2; d <<= 1) {
                    float om1 = __shfl_xor_sync(0xffffffffu, m1, d);
                    int   oi1 = __shfl_xor_sync(0xffffffffu, i1, d);
                    float om2 = __shfl_xor_sync(0xffffffffu, m2, d);
                    int   oi2 = __shfl_xor_sync(0xffffffffu, i2, d);
                    if (om1 > m1) {
                        if (m1 >= om2) { m2 = m1; i2 = i1; }
                        else           { m2 = om2; i2 = oi2; }
                        m1 = om1; i1 = oi1;
                    } else if (om1 > m2) { m2 = om1; i2 = oi1; }
                }
                float g1 = 1.f / (1.f + __expf(m2 - m1));
                float g2 = 1.f - g1;
                int row = wm * 32 + mt * 16 + half * 8 + g;
                gw[row * 8 + 2 * tig]     = (2 * tig     == i1) ? g1 : ((2 * tig     == i2) ? g2 : 0.f);
                gw[row * 8 + 2 * tig + 1] = (2 * tig + 1 == i1) ? g1 : ((2 * tig + 1 == i2) ? g2 : 0.f);
            }
        }
    }
    __syncthreads();

    // ---- gate h, pack fp16, store in GEMM2 A-fragment order (no shuffles) ----
    // C-frag value (r=g[+8], c=nt*8+2tig[+1]) lands at dest lane g*4+tig,
    // reg = (r>>3) + 2*(nt&1)  -> the two row-regs are adjacent: one STG.64.
#pragma unroll
    for (int mt = 0; mt < 2; ++mt) {
#pragma unroll
        for (int nt = 0; nt < 8; ++nt) {
            const int col = ncol0 + nt * 8 + 2 * tig;
            const int e  = col >> 4;
            const int ra = wm * 32 + mt * 16 + g;
            const float wa = gw[ra * 8 + e];
            const float wb = gw[(ra + 8) * 8 + e];
            uint32_t w0 = pack_f16x2(acc[mt][nt][0] * wa, acc[mt][nt][1] * wa);
            uint32_t w1 = pack_f16x2(acc[mt][nt][2] * wb, acc[mt][nt][3] * wb);
            const int m16 = (m0 + wm * 32 + mt * 16) >> 4;
            const int k16 = wn * 4 + (nt >> 1);
            *(uint2*)(g_hwf + ((size_t)m16 * 8 + k16) * 128
                            + lane * 4 + 2 * (nt & 1)) = make_uint2(w0, w1);
        }
    }
}

// ============================================================================
// GEMM2: out[N,4096] = hw @ Bt^T (fp16 mma). Block 256m x 128n, warp 64x64.
// B frag-major in 32KB SMEM (LDS.64); A-frags via LDG.128 from L2-resident
// g_hwf. No syncthreads in the m-sweep.
// ============================================================================
#define SM2_WORDS (16 * 8 * 64)    // 8192 words = 32 KB

__global__ __launch_bounds__(256, 1)
void gemm2_kernel(float* __restrict__ out)
{
    extern __shared__ uint32_t Bs[];   // [16 n8][8 k16][64]

    const int tid  = threadIdx.x;
    const int lane = tid & 31;
    const int warp = tid >> 5;
    const int wm   = warp & 3;        // 4 m-groups of 64 rows
    const int wn   = warp >> 2;       // 2 n-groups of 64 cols
    const int nb   = blockIdx.x & 31; // n-block (128 cols)
    const int mc   = blockIdx.x >> 5; // 0..3, 16 m-tiles (256 rows) each

    // ---- Bs once: contiguous 8192-word slab of g_btf ----
#pragma unroll
    for (int i = 0; i < 8; i++) {
        int idx = tid + i * 256;
        cp16(Bs + idx * 4, g_btf + (size_t)nb * 8192 + idx * 4);
    }
    CP_COMMIT(); CP_WAIT(0);
    __syncthreads();

    const int n0 = nb * 128;
    for (int it = 0; it < 16; ++it) {
        const int mti  = mc * 16 + it;            // 256-row tile index
        const int m16b = mti * 16 + wm * 4;       // first m16 block for warp

        float acc[4][8][4];
#pragma unroll
        for (int mt = 0; mt < 4; mt++)
#pragma unroll
            for (int nt = 0; nt < 8; nt++)
#pragma unroll
                for (int i = 0; i < 4; i++) acc[mt][nt][i] = 0.f;

        uint4 af[4];
#pragma unroll
        for (int mt = 0; mt < 4; mt++)
            af[mt] = *(const uint4*)(g_hwf + ((size_t)(m16b + mt) * 8 + 0) * 128 + lane * 4);

#pragma unroll
        for (int ks = 0; ks < 8; ++ks) {
            uint4 afn[4];
            if (ks < 7) {
#pragma unroll
                for (int mt = 0; mt < 4; mt++)
                    afn[mt] = *(const uint4*)(g_hwf + ((size_t)(m16b + mt) * 8 + ks + 1) * 128 + lane * 4);
            }
            uint2 bf[8];
#pragma unroll
            for (int nt = 0; nt < 8; nt++) {
                const int n8l = wn * 8 + nt;
                bf[nt] = *(const uint2*)(Bs + (n8l * 8 + ks) * 64 + lane * 2);
            }
#pragma unroll
            for (int nt = 0; nt < 8; nt++)
#pragma unroll
                for (int mt = 0; mt < 4; mt++)
                    mma_f16(acc[mt][nt], (const uint32_t*)&af[mt], bf[nt].x, bf[nt].y);
            if (ks < 7) {
#pragma unroll
                for (int mt = 0; mt < 4; mt++) af[mt] = afn[mt];
            }
        }

        const int g   = lane >> 2;
        const int tig = lane & 3;
#pragma unroll
        for (int mt = 0; mt < 4; ++mt) {
#pragma unroll
            for (int nt = 0; nt < 8; ++nt) {
                const int col = n0 + wn * 64 + nt * 8 + 2 * tig;
                const int ra  = mti * 256 + wm * 64 + mt * 16 + g;
                *(float2*)(out + (size_t)ra * OUT_D + col) =
                    make_float2(acc[mt][nt][0], acc[mt][nt][1]);
                *(float2*)(out + (size_t)(ra + 8) * OUT_D + col) =
                    make_float2(acc[mt][nt][2], acc[mt][nt][3]);
            }
        }
    }
}

// ============================================================================
extern "C" void kernel_launch(void* const* d_in, const int* in_sizes, int n_in,
                              void* d_out, int out_size)
{
    const float* x  = (const float*)d_in[0];   // [N, 4096]
    const float* rw = (const float*)d_in[1];   // [8, 4096]
    const float* rb = (const float*)d_in[2];   // [8]
    const float* A  = (const float*)d_in[3];   // [8,16,4096]
    const float* Bm = (const float*)d_in[4];   // [8,4096,16]
    float* out = (float*)d_out;                // [N, 4096] fp32

    const int sm1 = SM1_WORDS * 4;   // 110592 B
    const int sm2 = SM2_WORDS * 4;   // 32768 B
    cudaFuncSetAttribute(gemm1_kernel,
                         cudaFuncAttributeMaxDynamicSharedMemorySize, sm1);
    cudaFuncSetAttribute(gemm2_kernel,
                         cudaFuncAttributeMaxDynamicSharedMemorySize, sm2);

    prep_kernel<<<1024, 256>>>(rw, A, Bm);
    gemm1_kernel<<<N_TOK / 128, 256, sm1>>>(x, rb);
    gemm2_kernel<<<128, 256, sm2>>>(out);
}